// round 1
// baseline (speedup 1.0000x reference)
#include <cuda_runtime.h>

// LIF layer: spk_seq = scan over T of thresholded leaky integrator fed by
// cur = X @ W^T + b.
// Shapes: x_seq (T=64, B=128, IN=2048), W (OUT=2048, IN=2048), b (2048)
// Output: (T, B, OUT) float32 spikes in {0,1}.

constexpr int T_DIM  = 64;
constexpr int B_DIM  = 128;
constexpr int IN_DIM = 2048;
constexpr int OUT_DIM = 2048;
constexpr int M_DIM  = T_DIM * B_DIM;   // 8192 GEMM rows
constexpr float THR_V   = 1.0f;
// exp(-1/TAU) with TAU=2.0, rounded to nearest fp32
constexpr float DECAY_V = 0.60653065971263342f;

// 64 MB scratch for the pre-activation currents (allocation-free rule:
// __device__ global array, lives in module memory).
__device__ float g_cur[(size_t)M_DIM * OUT_DIM];

// ---------------------------------------------------------------------------
// GEMM-NT: C[m,n] = sum_k A[m,k] * W[n,k]
// BM=BN=128, BK=8, per-thread 8x8 register tile, 256 threads/CTA.
// ---------------------------------------------------------------------------
constexpr int BM = 128, BN = 128, BK = 8, TM = 8, TN = 8;

__global__ __launch_bounds__(256, 2)
void gemm_nt_kernel(const float* __restrict__ A,
                    const float* __restrict__ W)
{
    __shared__ float As[BK][BM];
    __shared__ float Bs[BK][BN];

    const int tid = threadIdx.x;
    const int bm  = blockIdx.y * BM;
    const int bn  = blockIdx.x * BN;

    // Tile-load mapping: each thread loads one float4 of A and one of W.
    const int lr = tid >> 1;          // row within 128-row tile
    const int lc = (tid & 1) * 4;     // k-offset: 0 or 4

    // Compute mapping: 16x16 thread grid, 8x8 outputs each.
    const int tx = tid & 15;
    const int ty = tid >> 4;

    const float* Aptr = A + (size_t)(bm + lr) * IN_DIM + lc;
    const float* Wptr = W + (size_t)(bn + lr) * IN_DIM + lc;

    float acc[TM][TN];
#pragma unroll
    for (int i = 0; i < TM; i++)
#pragma unroll
        for (int j = 0; j < TN; j++) acc[i][j] = 0.0f;

    for (int k0 = 0; k0 < IN_DIM; k0 += BK) {
        float4 a4 = *reinterpret_cast<const float4*>(Aptr + k0);
        float4 b4 = *reinterpret_cast<const float4*>(Wptr + k0);
        As[lc + 0][lr] = a4.x; As[lc + 1][lr] = a4.y;
        As[lc + 2][lr] = a4.z; As[lc + 3][lr] = a4.w;
        Bs[lc + 0][lr] = b4.x; Bs[lc + 1][lr] = b4.y;
        Bs[lc + 2][lr] = b4.z; Bs[lc + 3][lr] = b4.w;
        __syncthreads();

#pragma unroll
        for (int k = 0; k < BK; k++) {
            float4 a0 = *reinterpret_cast<const float4*>(&As[k][ty * TM]);
            float4 a1 = *reinterpret_cast<const float4*>(&As[k][ty * TM + 4]);
            float4 b0 = *reinterpret_cast<const float4*>(&Bs[k][tx * TN]);
            float4 b1 = *reinterpret_cast<const float4*>(&Bs[k][tx * TN + 4]);
            float ar[TM] = {a0.x, a0.y, a0.z, a0.w, a1.x, a1.y, a1.z, a1.w};
            float br[TN] = {b0.x, b0.y, b0.z, b0.w, b1.x, b1.y, b1.z, b1.w};
#pragma unroll
            for (int i = 0; i < TM; i++)
#pragma unroll
                for (int j = 0; j < TN; j++)
                    acc[i][j] = fmaf(ar[i], br[j], acc[i][j]);
        }
        __syncthreads();
    }

    // Epilogue: store to scratch (row-major [M, OUT]).
#pragma unroll
    for (int i = 0; i < TM; i++) {
        float* Cp = g_cur + (size_t)(bm + ty * TM + i) * OUT_DIM + bn + tx * TN;
        float4 v0 = make_float4(acc[i][0], acc[i][1], acc[i][2], acc[i][3]);
        float4 v1 = make_float4(acc[i][4], acc[i][5], acc[i][6], acc[i][7]);
        *reinterpret_cast<float4*>(Cp)     = v0;
        *reinterpret_cast<float4*>(Cp + 4) = v1;
    }
}

// ---------------------------------------------------------------------------
// LIF scan: one thread per (b, o) neuron, sequential over T.
// Rounding is kept bit-identical to the reference ordering:
//   cur = gemm + bias   (one round)
//   mem = (mem * decay) + cur   (two separately rounded ops, NOT fused)
//   spk = (mem - THR) > 0
//   mem = mem - spk * THR
// ---------------------------------------------------------------------------
__global__ __launch_bounds__(256)
void lif_scan_kernel(const float* __restrict__ bias,
                     float* __restrict__ out)
{
    const int idx = blockIdx.x * blockDim.x + threadIdx.x; // 0 .. B*OUT-1
    const int BO  = B_DIM * OUT_DIM;
    if (idx >= BO) return;

    const float bi = bias[idx & (OUT_DIM - 1)];
    float mem = 0.0f;

#pragma unroll
    for (int t = 0; t < T_DIM; t++) {
        float c = __fadd_rn(g_cur[(size_t)t * BO + idx], bi);
        mem = __fadd_rn(__fmul_rn(mem, DECAY_V), c);
        float spk = (__fadd_rn(mem, -THR_V) > 0.0f) ? 1.0f : 0.0f;
        mem = __fadd_rn(mem, -spk * THR_V);
        out[(size_t)t * BO + idx] = spk;
    }
}

// ---------------------------------------------------------------------------
extern "C" void kernel_launch(void* const* d_in, const int* in_sizes, int n_in,
                              void* d_out, int out_size)
{
    const float* x = (const float*)d_in[0];   // (T, B, IN) -> (M, IN)
    const float* W = (const float*)d_in[1];   // (OUT, IN)
    const float* b = (const float*)d_in[2];   // (OUT,)
    float* out = (float*)d_out;               // (T, B, OUT)

    dim3 ggrid(OUT_DIM / BN, M_DIM / BM);     // (16, 64)
    gemm_nt_kernel<<<ggrid, 256>>>(x, W);

    const int BO = B_DIM * OUT_DIM;           // 262144
    lif_scan_kernel<<<BO / 256, 256>>>(b, out);
}

// round 5
// speedup vs baseline: 1.1818x; 1.1818x over previous
#include <cuda_runtime.h>
#include <cuda_bf16.h>
#include <cstdint>

// ---------------------------------------------------------------------------
// LIF layer: cur = X @ W^T + b via bf16x3-split GEMM on mma.sync (HMMA).
// Numerics: main a0*b0 path uses zero-C mma per k16 chunk, drained into fp32
// registers with Kahan (Fast TwoSum) compensation. The 5 small split-combos
// chain in a TC accumulator that is flushed (Kahan) into the main accumulator
// every 8 ktiles to bound RZ drift.
// ---------------------------------------------------------------------------

constexpr int T_DIM  = 64;
constexpr int B_DIM  = 128;
constexpr int IN_DIM = 2048;
constexpr int OUT_DIM = 2048;
constexpr int M_DIM  = T_DIM * B_DIM;          // 8192
constexpr float THR_V   = 1.0f;
constexpr float DECAY_V = 0.60653065971263342f; // exp(-1/2) rounded to fp32

// ------------------------------ scratch -----------------------------------
__device__ float g_cur[(size_t)M_DIM * OUT_DIM];                 // 64 MB
__device__ __nv_bfloat16 g_A0[(size_t)M_DIM * IN_DIM];           // 32 MB each
__device__ __nv_bfloat16 g_A1[(size_t)M_DIM * IN_DIM];
__device__ __nv_bfloat16 g_A2[(size_t)M_DIM * IN_DIM];
__device__ __nv_bfloat16 g_B0[(size_t)OUT_DIM * IN_DIM];         // 8 MB each
__device__ __nv_bfloat16 g_B1[(size_t)OUT_DIM * IN_DIM];
__device__ __nv_bfloat16 g_B2[(size_t)OUT_DIM * IN_DIM];

// ------------------------------ helpers -----------------------------------
__device__ __forceinline__ uint32_t smem_u32(const void* p) {
    uint32_t a;
    asm("{ .reg .u64 t; cvta.to.shared.u64 t, %1; cvt.u32.u64 %0, t; }"
        : "=r"(a) : "l"(p));
    return a;
}

#define SW128(o) ((o) ^ (((o) >> 3) & 0x70))

__device__ __forceinline__ void ldmx4(uint32_t* r, uint32_t addr) {
    asm volatile("ldmatrix.sync.aligned.m8n8.x4.shared.b16 {%0,%1,%2,%3}, [%4];"
                 : "=r"(r[0]), "=r"(r[1]), "=r"(r[2]), "=r"(r[3]) : "r"(addr));
}
// chained accumulate
__device__ __forceinline__ void mma16816(float* d, const uint32_t* a,
                                         const uint32_t* b) {
    asm volatile(
        "mma.sync.aligned.m16n8k16.row.col.f32.bf16.bf16.f32 "
        "{%0,%1,%2,%3}, {%4,%5,%6,%7}, {%8,%9}, {%0,%1,%2,%3};"
        : "+f"(d[0]), "+f"(d[1]), "+f"(d[2]), "+f"(d[3])
        : "r"(a[0]), "r"(a[1]), "r"(a[2]), "r"(a[3]), "r"(b[0]), "r"(b[1]));
}
// zero-C form: D = A*B
__device__ __forceinline__ void mma16816_z(float* d, const uint32_t* a,
                                           const uint32_t* b) {
    asm volatile(
        "mma.sync.aligned.m16n8k16.row.col.f32.bf16.bf16.f32 "
        "{%0,%1,%2,%3}, {%4,%5,%6,%7}, {%8,%9}, {%10,%11,%12,%13};"
        : "=f"(d[0]), "=f"(d[1]), "=f"(d[2]), "=f"(d[3])
        : "r"(a[0]), "r"(a[1]), "r"(a[2]), "r"(a[3]), "r"(b[0]), "r"(b[1]),
          "f"(0.0f), "f"(0.0f), "f"(0.0f), "f"(0.0f));
}

// Kahan (Fast TwoSum) compensated add: a += v, error into c.
__device__ __forceinline__ void kadd(float& a, float& c, float v) {
    float s = __fadd_rn(a, v);
    float z = __fadd_rn(s, -a);       // the part of v that made it in
    c = __fadd_rn(c, __fadd_rn(v, -z));
    a = s;
}

// ------------------------- split fp32 -> 3x bf16 ---------------------------
__device__ __forceinline__ void split3(float v, __nv_bfloat16& h0,
                                       __nv_bfloat16& h1, __nv_bfloat16& h2) {
    h0 = __float2bfloat16(v);
    float r1 = v - __bfloat162float(h0);
    h1 = __float2bfloat16(r1);
    float r2 = r1 - __bfloat162float(h1);
    h2 = __float2bfloat16(r2);
}

__global__ __launch_bounds__(256) void split_x_kernel(const float* __restrict__ src)
{
    int i = blockIdx.x * blockDim.x + threadIdx.x;   // one float4 per thread
    float4 a = reinterpret_cast<const float4*>(src)[i];
    float v[4] = {a.x, a.y, a.z, a.w};
    __nv_bfloat16 h0[4], h1[4], h2[4];
#pragma unroll
    for (int j = 0; j < 4; j++) split3(v[j], h0[j], h1[j], h2[j]);
    __nv_bfloat162 p;
    p = {h0[0], h0[1]}; reinterpret_cast<__nv_bfloat162*>(g_A0)[2*i  ] = p;
    p = {h0[2], h0[3]}; reinterpret_cast<__nv_bfloat162*>(g_A0)[2*i+1] = p;
    p = {h1[0], h1[1]}; reinterpret_cast<__nv_bfloat162*>(g_A1)[2*i  ] = p;
    p = {h1[2], h1[3]}; reinterpret_cast<__nv_bfloat162*>(g_A1)[2*i+1] = p;
    p = {h2[0], h2[1]}; reinterpret_cast<__nv_bfloat162*>(g_A2)[2*i  ] = p;
    p = {h2[2], h2[3]}; reinterpret_cast<__nv_bfloat162*>(g_A2)[2*i+1] = p;
}

__global__ __launch_bounds__(256) void split_w_kernel(const float* __restrict__ src)
{
    int i = blockIdx.x * blockDim.x + threadIdx.x;
    float4 a = reinterpret_cast<const float4*>(src)[i];
    float v[4] = {a.x, a.y, a.z, a.w};
    __nv_bfloat16 h0[4], h1[4], h2[4];
#pragma unroll
    for (int j = 0; j < 4; j++) split3(v[j], h0[j], h1[j], h2[j]);
    __nv_bfloat162 p;
    p = {h0[0], h0[1]}; reinterpret_cast<__nv_bfloat162*>(g_B0)[2*i  ] = p;
    p = {h0[2], h0[3]}; reinterpret_cast<__nv_bfloat162*>(g_B0)[2*i+1] = p;
    p = {h1[0], h1[1]}; reinterpret_cast<__nv_bfloat162*>(g_B1)[2*i  ] = p;
    p = {h1[2], h1[3]}; reinterpret_cast<__nv_bfloat162*>(g_B1)[2*i+1] = p;
    p = {h2[0], h2[1]}; reinterpret_cast<__nv_bfloat162*>(g_B2)[2*i  ] = p;
    p = {h2[2], h2[3]}; reinterpret_cast<__nv_bfloat162*>(g_B2)[2*i+1] = p;
}

// ------------------------------ GEMM kernel --------------------------------
constexpr int BM = 128, BN = 128, BK = 64;
constexpr int NST = IN_DIM / BK;              // 32 ktiles
constexpr int TILE_B = 128 * 128;             // 16 KB per tile (SW128 rows)
constexpr int SMEM_SZ = 12 * TILE_B;          // 196608 B, double-buffered

__global__ __launch_bounds__(256, 1)
void lif_gemm_kernel(const float* __restrict__ bias)
{
    extern __shared__ char smem[];
    const uint32_t sb = smem_u32(smem);
    const int tid  = threadIdx.x;
    const int wid  = tid >> 5;
    const int lane = tid & 31;
    const int bm = blockIdx.y * BM;
    const int bn = blockIdx.x * BN;
    const int warp_m = wid & 3;      // 0..3
    const int warp_n = wid >> 2;     // 0..1

    const __nv_bfloat16* src[6] = {
        g_A0 + (size_t)bm * IN_DIM, g_A1 + (size_t)bm * IN_DIM,
        g_A2 + (size_t)bm * IN_DIM,
        g_B0 + (size_t)bn * IN_DIM, g_B1 + (size_t)bn * IN_DIM,
        g_B2 + (size_t)bn * IN_DIM };

    auto stage_load = [&](int s) {
        const int buf = s & 1;
        const int k0 = s * BK;
#pragma unroll
        for (int t = 0; t < 6; t++) {
            const __nv_bfloat16* base = src[t] + k0;
            uint32_t stile = sb + (buf * 6 + t) * TILE_B;
#pragma unroll
            for (int u = 0; u < 4; u++) {
                int v = tid + 256 * u;          // 0..1023
                int row = v >> 3;
                int c = (v & 7) * 16;           // byte col within 128B row
                const void* g = (const char*)(base + (size_t)row * IN_DIM) + c;
                uint32_t d = stile + SW128(row * 128 + c);
                asm volatile("cp.async.cg.shared.global [%0], [%1], 16;"
                             :: "r"(d), "l"(g));
            }
        }
        asm volatile("cp.async.commit_group;" ::: "memory");
    };

    float acc[2][8][4];   // fp32 Kahan sum (everything ends up here)
    float cmp[2][8][4];   // Kahan compensation
    float accs[2][8][4];  // TC-chained small-combo accumulator (flushed /8 ktiles)
#pragma unroll
    for (int mt = 0; mt < 2; mt++)
#pragma unroll
        for (int nt = 0; nt < 8; nt++)
#pragma unroll
            for (int j = 0; j < 4; j++) {
                acc[mt][nt][j] = 0.0f; cmp[mt][nt][j] = 0.0f; accs[mt][nt][j] = 0.0f;
            }

    stage_load(0);

    const int mi = lane >> 3, r8 = lane & 7;   // ldmatrix address split

    for (int s = 0; s < NST; s++) {
        if (s + 1 < NST) {
            stage_load(s + 1);
            asm volatile("cp.async.wait_group 1;" ::: "memory");
        } else {
            asm volatile("cp.async.wait_group 0;" ::: "memory");
        }
        __syncthreads();

        const uint32_t sbase = sb + (s & 1) * 6 * TILE_B;
        const bool group_start = ((s & 7) == 0);   // restart small chain

#pragma unroll 1
        for (int ks = 0; ks < 4; ks++) {       // 4 x k16 steps per ktile
            // A fragments for all 3 splits
            uint32_t af[3][2][4];
#pragma unroll
            for (int t = 0; t < 3; t++)
#pragma unroll
                for (int mt = 0; mt < 2; mt++) {
                    int row = warp_m * 32 + mt * 16 + (mi & 1) * 8 + r8;
                    int kb  = ks * 32 + (mi >> 1) * 16;
                    ldmx4(af[t][mt], sbase + t * TILE_B + SW128(row * 128 + kb));
                }

            uint32_t bfr[4][4];                // one B split at a time
            const int nrow = warp_n * 64 + (mi >> 1) * 8 + r8;
            const int kb   = ks * 32 + (mi & 1) * 16;

            // ---- B split 0 ----
#pragma unroll
            for (int np = 0; np < 4; np++)
                ldmx4(bfr[np], sbase + 3 * TILE_B + SW128((nrow + np * 16) * 128 + kb));
            // main path a0*b0 with Kahan drain
#pragma unroll
            for (int mt = 0; mt < 2; mt++)
#pragma unroll
                for (int nt = 0; nt < 8; nt++) {
                    float tmp[4];
                    mma16816_z(tmp, af[0][mt], &bfr[nt >> 1][(nt & 1) * 2]);
#pragma unroll
                    for (int j = 0; j < 4; j++)
                        kadd(acc[mt][nt][j], cmp[mt][nt][j], tmp[j]);
                }
            // small: a1*b0 (restarts the chain at group start), a2*b0
            if (group_start && ks == 0) {
#pragma unroll
                for (int mt = 0; mt < 2; mt++)
#pragma unroll
                    for (int nt = 0; nt < 8; nt++)
                        mma16816_z(accs[mt][nt], af[1][mt], &bfr[nt >> 1][(nt & 1) * 2]);
            } else {
#pragma unroll
                for (int mt = 0; mt < 2; mt++)
#pragma unroll
                    for (int nt = 0; nt < 8; nt++)
                        mma16816(accs[mt][nt], af[1][mt], &bfr[nt >> 1][(nt & 1) * 2]);
            }
#pragma unroll
            for (int mt = 0; mt < 2; mt++)
#pragma unroll
                for (int nt = 0; nt < 8; nt++)
                    mma16816(accs[mt][nt], af[2][mt], &bfr[nt >> 1][(nt & 1) * 2]);

            // ---- B split 1: a0*b1, a1*b1 ----
#pragma unroll
            for (int np = 0; np < 4; np++)
                ldmx4(bfr[np], sbase + 4 * TILE_B + SW128((nrow + np * 16) * 128 + kb));
#pragma unroll
            for (int mt = 0; mt < 2; mt++)
#pragma unroll
                for (int nt = 0; nt < 8; nt++)
                    mma16816(accs[mt][nt], af[0][mt], &bfr[nt >> 1][(nt & 1) * 2]);
#pragma unroll
            for (int mt = 0; mt < 2; mt++)
#pragma unroll
                for (int nt = 0; nt < 8; nt++)
                    mma16816(accs[mt][nt], af[1][mt], &bfr[nt >> 1][(nt & 1) * 2]);

            // ---- B split 2: a0*b2 ----
#pragma unroll
            for (int np = 0; np < 4; np++)
                ldmx4(bfr[np], sbase + 5 * TILE_B + SW128((nrow + np * 16) * 128 + kb));
#pragma unroll
            for (int mt = 0; mt < 2; mt++)
#pragma unroll
                for (int nt = 0; nt < 8; nt++)
                    mma16816(accs[mt][nt], af[0][mt], &bfr[nt >> 1][(nt & 1) * 2]);
        }

        // flush small-combo chain every 8 ktiles (Kahan into main sum)
        if ((s & 7) == 7) {
#pragma unroll
            for (int mt = 0; mt < 2; mt++)
#pragma unroll
                for (int nt = 0; nt < 8; nt++)
#pragma unroll
                    for (int j = 0; j < 4; j++)
                        kadd(acc[mt][nt][j], cmp[mt][nt][j], accs[mt][nt][j]);
        }
        __syncthreads();
    }

    // Epilogue: acc + cmp + bias, store fp32 currents.
    const int qr = lane >> 2;
    const int qc = (lane & 3) * 2;
#pragma unroll
    for (int mt = 0; mt < 2; mt++)
#pragma unroll
        for (int h = 0; h < 2; h++) {
            int row = bm + warp_m * 32 + mt * 16 + h * 8 + qr;
            float* dst = g_cur + (size_t)row * OUT_DIM + bn + warp_n * 64 + qc;
            const float* bp = bias + bn + warp_n * 64 + qc;
#pragma unroll
            for (int nt = 0; nt < 8; nt++) {
                float2 v;
                v.x = __fadd_rn(__fadd_rn(acc[mt][nt][h * 2 + 0], cmp[mt][nt][h * 2 + 0]),
                                bp[nt * 8 + 0]);
                v.y = __fadd_rn(__fadd_rn(acc[mt][nt][h * 2 + 1], cmp[mt][nt][h * 2 + 1]),
                                bp[nt * 8 + 1]);
                *reinterpret_cast<float2*>(dst + nt * 8) = v;
            }
        }
}

// ------------------------------ LIF scan -----------------------------------
__global__ __launch_bounds__(256) void lif_scan_kernel(float* __restrict__ out)
{
    const int idx = blockIdx.x * blockDim.x + threadIdx.x; // 0 .. B*OUT-1
    const int BO  = B_DIM * OUT_DIM;
    float mem = 0.0f;
#pragma unroll
    for (int t = 0; t < T_DIM; t++) {
        float c = g_cur[(size_t)t * BO + idx];   // bias already folded in
        mem = __fadd_rn(__fmul_rn(mem, DECAY_V), c);
        float spk = (__fadd_rn(mem, -THR_V) > 0.0f) ? 1.0f : 0.0f;
        mem = __fadd_rn(mem, -spk * THR_V);
        out[(size_t)t * BO + idx] = spk;
    }
}

// ---------------------------------------------------------------------------
extern "C" void kernel_launch(void* const* d_in, const int* in_sizes, int n_in,
                              void* d_out, int out_size)
{
    const float* x = (const float*)d_in[0];   // (T,B,IN) = (M, IN)
    const float* W = (const float*)d_in[1];   // (OUT, IN)
    const float* b = (const float*)d_in[2];   // (OUT,)
    float* out = (float*)d_out;               // (T,B,OUT)

    split_x_kernel<<<(M_DIM * (size_t)IN_DIM / 4) / 256, 256>>>(x);
    split_w_kernel<<<(OUT_DIM * (size_t)IN_DIM / 4) / 256, 256>>>(W);

    cudaFuncSetAttribute(lif_gemm_kernel,
                         cudaFuncAttributeMaxDynamicSharedMemorySize, SMEM_SZ);
    dim3 grid(OUT_DIM / BN, M_DIM / BM);      // (16, 64)
    lif_gemm_kernel<<<grid, 256, SMEM_SZ>>>(b);

    lif_scan_kernel<<<(B_DIM * OUT_DIM) / 256, 256>>>(out);
}

// round 6
// speedup vs baseline: 1.4473x; 1.2246x over previous
#include <cuda_runtime.h>
#include <cuda_bf16.h>
#include <cstdint>

// ---------------------------------------------------------------------------
// LIF layer: cur = X @ W^T + b via bf16x3-split GEMM on mma.sync (HMMA).
// R6: two GEMM kernels to kill register spills + halve Kahan FADD work.
//  K1: main a0*b0 path. Chain-2 in TC (zero-C + 1 chained mma), Kahan drain
//      into fp32 regs. Writes g_cur = main + bias.
//  K2: 5 small split-combos, TC-chained into 2 accumulator sets (k halves),
//      epilogue does g_cur += smalls.
// ---------------------------------------------------------------------------

constexpr int T_DIM  = 64;
constexpr int B_DIM  = 128;
constexpr int IN_DIM = 2048;
constexpr int OUT_DIM = 2048;
constexpr int M_DIM  = T_DIM * B_DIM;          // 8192
constexpr float THR_V   = 1.0f;
constexpr float DECAY_V = 0.60653065971263342f; // exp(-1/2) rounded to fp32

// ------------------------------ scratch -----------------------------------
__device__ float g_cur[(size_t)M_DIM * OUT_DIM];                 // 64 MB
__device__ __nv_bfloat16 g_A0[(size_t)M_DIM * IN_DIM];           // 32 MB each
__device__ __nv_bfloat16 g_A1[(size_t)M_DIM * IN_DIM];
__device__ __nv_bfloat16 g_A2[(size_t)M_DIM * IN_DIM];
__device__ __nv_bfloat16 g_B0[(size_t)OUT_DIM * IN_DIM];         // 8 MB each
__device__ __nv_bfloat16 g_B1[(size_t)OUT_DIM * IN_DIM];
__device__ __nv_bfloat16 g_B2[(size_t)OUT_DIM * IN_DIM];

// ------------------------------ helpers -----------------------------------
__device__ __forceinline__ uint32_t smem_u32(const void* p) {
    uint32_t a;
    asm("{ .reg .u64 t; cvta.to.shared.u64 t, %1; cvt.u32.u64 %0, t; }"
        : "=r"(a) : "l"(p));
    return a;
}

#define SW128(o) ((o) ^ (((o) >> 3) & 0x70))

__device__ __forceinline__ void ldmx4(uint32_t* r, uint32_t addr) {
    asm volatile("ldmatrix.sync.aligned.m8n8.x4.shared.b16 {%0,%1,%2,%3}, [%4];"
                 : "=r"(r[0]), "=r"(r[1]), "=r"(r[2]), "=r"(r[3]) : "r"(addr));
}
// chained accumulate: d += a*b
__device__ __forceinline__ void mma16816(float* d, const uint32_t* a,
                                         const uint32_t* b) {
    asm volatile(
        "mma.sync.aligned.m16n8k16.row.col.f32.bf16.bf16.f32 "
        "{%0,%1,%2,%3}, {%4,%5,%6,%7}, {%8,%9}, {%0,%1,%2,%3};"
        : "+f"(d[0]), "+f"(d[1]), "+f"(d[2]), "+f"(d[3])
        : "r"(a[0]), "r"(a[1]), "r"(a[2]), "r"(a[3]), "r"(b[0]), "r"(b[1]));
}
// zero-C form: d = a*b
__device__ __forceinline__ void mma16816_z(float* d, const uint32_t* a,
                                           const uint32_t* b) {
    asm volatile(
        "mma.sync.aligned.m16n8k16.row.col.f32.bf16.bf16.f32 "
        "{%0,%1,%2,%3}, {%4,%5,%6,%7}, {%8,%9}, {%10,%11,%12,%13};"
        : "=f"(d[0]), "=f"(d[1]), "=f"(d[2]), "=f"(d[3])
        : "r"(a[0]), "r"(a[1]), "r"(a[2]), "r"(a[3]), "r"(b[0]), "r"(b[1]),
          "f"(0.0f), "f"(0.0f), "f"(0.0f), "f"(0.0f));
}
// Kahan (Fast TwoSum) compensated add: a += v, error into c.
__device__ __forceinline__ void kadd(float& a, float& c, float v) {
    float s = __fadd_rn(a, v);
    float z = __fadd_rn(s, -a);
    c = __fadd_rn(c, __fadd_rn(v, -z));
    a = s;
}

// ------------------------- split fp32 -> 3x bf16 ---------------------------
__device__ __forceinline__ void split3(float v, __nv_bfloat16& h0,
                                       __nv_bfloat16& h1, __nv_bfloat16& h2) {
    h0 = __float2bfloat16(v);
    float r1 = v - __bfloat162float(h0);
    h1 = __float2bfloat16(r1);
    float r2 = r1 - __bfloat162float(h1);
    h2 = __float2bfloat16(r2);
}

__global__ __launch_bounds__(256) void split_x_kernel(const float* __restrict__ src)
{
    int i = blockIdx.x * blockDim.x + threadIdx.x;
    float4 a = reinterpret_cast<const float4*>(src)[i];
    float v[4] = {a.x, a.y, a.z, a.w};
    __nv_bfloat16 h0[4], h1[4], h2[4];
#pragma unroll
    for (int j = 0; j < 4; j++) split3(v[j], h0[j], h1[j], h2[j]);
    __nv_bfloat162 p;
    p = {h0[0], h0[1]}; reinterpret_cast<__nv_bfloat162*>(g_A0)[2*i  ] = p;
    p = {h0[2], h0[3]}; reinterpret_cast<__nv_bfloat162*>(g_A0)[2*i+1] = p;
    p = {h1[0], h1[1]}; reinterpret_cast<__nv_bfloat162*>(g_A1)[2*i  ] = p;
    p = {h1[2], h1[3]}; reinterpret_cast<__nv_bfloat162*>(g_A1)[2*i+1] = p;
    p = {h2[0], h2[1]}; reinterpret_cast<__nv_bfloat162*>(g_A2)[2*i  ] = p;
    p = {h2[2], h2[3]}; reinterpret_cast<__nv_bfloat162*>(g_A2)[2*i+1] = p;
}

__global__ __launch_bounds__(256) void split_w_kernel(const float* __restrict__ src)
{
    int i = blockIdx.x * blockDim.x + threadIdx.x;
    float4 a = reinterpret_cast<const float4*>(src)[i];
    float v[4] = {a.x, a.y, a.z, a.w};
    __nv_bfloat16 h0[4], h1[4], h2[4];
#pragma unroll
    for (int j = 0; j < 4; j++) split3(v[j], h0[j], h1[j], h2[j]);
    __nv_bfloat162 p;
    p = {h0[0], h0[1]}; reinterpret_cast<__nv_bfloat162*>(g_B0)[2*i  ] = p;
    p = {h0[2], h0[3]}; reinterpret_cast<__nv_bfloat162*>(g_B0)[2*i+1] = p;
    p = {h1[0], h1[1]}; reinterpret_cast<__nv_bfloat162*>(g_B1)[2*i  ] = p;
    p = {h1[2], h1[3]}; reinterpret_cast<__nv_bfloat162*>(g_B1)[2*i+1] = p;
    p = {h2[0], h2[1]}; reinterpret_cast<__nv_bfloat162*>(g_B2)[2*i  ] = p;
    p = {h2[2], h2[3]}; reinterpret_cast<__nv_bfloat162*>(g_B2)[2*i+1] = p;
}

// ------------------------------ common dims --------------------------------
constexpr int BM = 128, BN = 128, BK = 64;
constexpr int NST = IN_DIM / BK;              // 32 ktiles
constexpr int TILE_B = 128 * 128;             // 16 KB per tile (SW128 rows)

// ============================ K1: main a0*b0 ================================
// 512 threads = 16 warps (4 wm x 4 wn), warp tile 32x32.
constexpr int K1_SMEM = 2 * TILE_B * 2;       // 65536 (A0,B0 double-buffered)

__global__ __launch_bounds__(512, 1)
void gemm_main_kernel(const float* __restrict__ bias)
{
    extern __shared__ char smem[];
    const uint32_t sb = smem_u32(smem);
    const int tid  = threadIdx.x;
    const int wid  = tid >> 5;
    const int lane = tid & 31;
    const int bm = blockIdx.y * BM;
    const int bn = blockIdx.x * BN;
    const int warp_m = wid & 3;
    const int warp_n = wid >> 2;

    const __nv_bfloat16* Asrc = g_A0 + (size_t)bm * IN_DIM;
    const __nv_bfloat16* Bsrc = g_B0 + (size_t)bn * IN_DIM;

    auto stage_load = [&](int s) {
        const int buf = s & 1;
        const int k0 = s * BK;
        uint32_t sA = sb + buf * 2 * TILE_B;
        uint32_t sB = sA + TILE_B;
#pragma unroll
        for (int u = 0; u < 2; u++) {
            int v = tid + 512 * u;              // 0..1023
            int row = v >> 3;
            int c = (v & 7) * 16;
            const void* ga = (const char*)(Asrc + (size_t)row * IN_DIM + k0) + c;
            const void* gb = (const char*)(Bsrc + (size_t)row * IN_DIM + k0) + c;
            uint32_t sw = SW128(row * 128 + c);
            asm volatile("cp.async.cg.shared.global [%0], [%1], 16;" :: "r"(sA + sw), "l"(ga));
            asm volatile("cp.async.cg.shared.global [%0], [%1], 16;" :: "r"(sB + sw), "l"(gb));
        }
        asm volatile("cp.async.commit_group;" ::: "memory");
    };

    float acc[2][4][4], cmp[2][4][4];
#pragma unroll
    for (int mt = 0; mt < 2; mt++)
#pragma unroll
        for (int nf = 0; nf < 4; nf++)
#pragma unroll
            for (int j = 0; j < 4; j++) { acc[mt][nf][j] = 0.0f; cmp[mt][nf][j] = 0.0f; }

    stage_load(0);
    const int mi = lane >> 3, r8 = lane & 7;

    for (int s = 0; s < NST; s++) {
        if (s + 1 < NST) {
            stage_load(s + 1);
            asm volatile("cp.async.wait_group 1;" ::: "memory");
        } else {
            asm volatile("cp.async.wait_group 0;" ::: "memory");
        }
        __syncthreads();

        const uint32_t sA = sb + (s & 1) * 2 * TILE_B;
        const uint32_t sB = sA + TILE_B;

#pragma unroll
        for (int kp = 0; kp < 2; kp++) {        // 2 chain-2 pairs per ktile
            uint32_t af[2][2][4];               // [kstep][mtile]
            uint32_t bfr[2][2][4];              // [kstep][npair16]
#pragma unroll
            for (int j = 0; j < 2; j++) {
                int kb_a = (kp * 2 + j) * 32 + (mi >> 1) * 16;
                int kb_b = (kp * 2 + j) * 32 + (mi & 1) * 16;
#pragma unroll
                for (int mt = 0; mt < 2; mt++) {
                    int row = warp_m * 32 + mt * 16 + (mi & 1) * 8 + r8;
                    ldmx4(af[j][mt], sA + SW128(row * 128 + kb_a));
                }
#pragma unroll
                for (int np = 0; np < 2; np++) {
                    int n = warp_n * 32 + np * 16 + (mi >> 1) * 8 + r8;
                    ldmx4(bfr[j][np], sB + SW128(n * 128 + kb_b));
                }
            }
#pragma unroll
            for (int mt = 0; mt < 2; mt++)
#pragma unroll
                for (int nf = 0; nf < 4; nf++) {
                    float tmp[4];
                    mma16816_z(tmp, af[0][mt], &bfr[0][nf >> 1][(nf & 1) * 2]);
                    mma16816 (tmp, af[1][mt], &bfr[1][nf >> 1][(nf & 1) * 2]);
#pragma unroll
                    for (int j = 0; j < 4; j++)
                        kadd(acc[mt][nf][j], cmp[mt][nf][j], tmp[j]);
                }
        }
        __syncthreads();
    }

    // Epilogue: main + cmp + bias -> g_cur
    const int qr = lane >> 2;
    const int qc = (lane & 3) * 2;
#pragma unroll
    for (int mt = 0; mt < 2; mt++)
#pragma unroll
        for (int h = 0; h < 2; h++) {
            int row = bm + warp_m * 32 + mt * 16 + h * 8 + qr;
            float* dst = g_cur + (size_t)row * OUT_DIM + bn + warp_n * 32 + qc;
            const float* bp = bias + bn + warp_n * 32 + qc;
#pragma unroll
            for (int nf = 0; nf < 4; nf++) {
                float2 v;
                v.x = __fadd_rn(__fadd_rn(acc[mt][nf][h*2+0], cmp[mt][nf][h*2+0]), bp[nf*8+0]);
                v.y = __fadd_rn(__fadd_rn(acc[mt][nf][h*2+1], cmp[mt][nf][h*2+1]), bp[nf*8+1]);
                *reinterpret_cast<float2*>(dst + nf * 8) = v;
            }
        }
}

// ====================== K2: 5 small split-combos ============================
// 512 threads = 16 warps, warp tile 32x32, 6 tiles per stage, double-buffered.
constexpr int K2_SMEM = 12 * TILE_B;          // 196608

__global__ __launch_bounds__(512, 1)
void gemm_small_kernel()
{
    extern __shared__ char smem[];
    const uint32_t sb = smem_u32(smem);
    const int tid  = threadIdx.x;
    const int wid  = tid >> 5;
    const int lane = tid & 31;
    const int bm = blockIdx.y * BM;
    const int bn = blockIdx.x * BN;
    const int warp_m = wid & 3;
    const int warp_n = wid >> 2;

    const __nv_bfloat16* src[6] = {
        g_A0 + (size_t)bm * IN_DIM, g_A1 + (size_t)bm * IN_DIM,
        g_A2 + (size_t)bm * IN_DIM,
        g_B0 + (size_t)bn * IN_DIM, g_B1 + (size_t)bn * IN_DIM,
        g_B2 + (size_t)bn * IN_DIM };

    auto stage_load = [&](int s) {
        const int buf = s & 1;
        const int k0 = s * BK;
#pragma unroll
        for (int t = 0; t < 6; t++) {
            const __nv_bfloat16* base = src[t] + k0;
            uint32_t stile = sb + (buf * 6 + t) * TILE_B;
#pragma unroll
            for (int u = 0; u < 2; u++) {
                int v = tid + 512 * u;          // 0..1023
                int row = v >> 3;
                int c = (v & 7) * 16;
                const void* g = (const char*)(base + (size_t)row * IN_DIM) + c;
                asm volatile("cp.async.cg.shared.global [%0], [%1], 16;"
                             :: "r"(stile + SW128(row * 128 + c)), "l"(g));
            }
        }
        asm volatile("cp.async.commit_group;" ::: "memory");
    };

    float accsA[2][4][4], accsB[2][4][4];
#pragma unroll
    for (int mt = 0; mt < 2; mt++)
#pragma unroll
        for (int nf = 0; nf < 4; nf++)
#pragma unroll
            for (int j = 0; j < 4; j++) { accsA[mt][nf][j] = 0.0f; accsB[mt][nf][j] = 0.0f; }

    stage_load(0);
    const int mi = lane >> 3, r8 = lane & 7;

    // body: one ktile of small combos chained into the given accumulator set
    auto body = [&](int s, float (&accs)[2][4][4]) {
        const uint32_t sbase = sb + (s & 1) * 6 * TILE_B;
#pragma unroll
        for (int ks = 0; ks < 4; ks++) {
            uint32_t af[3][2][4];
#pragma unroll
            for (int t = 0; t < 3; t++)
#pragma unroll
                for (int mt = 0; mt < 2; mt++) {
                    int row = warp_m * 32 + mt * 16 + (mi & 1) * 8 + r8;
                    int kb  = ks * 32 + (mi >> 1) * 16;
                    ldmx4(af[t][mt], sbase + t * TILE_B + SW128(row * 128 + kb));
                }
            const int kb_b = ks * 32 + (mi & 1) * 16;
            uint32_t bfr[2][4];
            // which a-splits pair with each b-split: b0:{a1,a2}, b1:{a0,a1}, b2:{a0}
            constexpr int NA[3]    = {2, 2, 1};
            constexpr int AI[3][2] = {{1, 2}, {0, 1}, {0, 0}};
#pragma unroll
            for (int bsp = 0; bsp < 3; bsp++) {
#pragma unroll
                for (int np = 0; np < 2; np++) {
                    int n = warp_n * 32 + np * 16 + (mi >> 1) * 8 + r8;
                    ldmx4(bfr[np], sbase + (3 + bsp) * TILE_B + SW128(n * 128 + kb_b));
                }
#pragma unroll
                for (int ai = 0; ai < 2; ai++) {
                    if (ai < NA[bsp]) {
#pragma unroll
                        for (int mt = 0; mt < 2; mt++)
#pragma unroll
                            for (int nf = 0; nf < 4; nf++)
                                mma16816(accs[mt][nf], af[AI[bsp][ai]][mt],
                                         &bfr[nf >> 1][(nf & 1) * 2]);
                    }
                }
            }
        }
    };

    for (int s = 0; s < NST; s++) {
        if (s + 1 < NST) {
            stage_load(s + 1);
            asm volatile("cp.async.wait_group 1;" ::: "memory");
        } else {
            asm volatile("cp.async.wait_group 0;" ::: "memory");
        }
        __syncthreads();
        if (s < NST / 2) body(s, accsA); else body(s, accsB);
        __syncthreads();
    }

    // Epilogue: g_cur += accsA + accsB
    const int qr = lane >> 2;
    const int qc = (lane & 3) * 2;
#pragma unroll
    for (int mt = 0; mt < 2; mt++)
#pragma unroll
        for (int h = 0; h < 2; h++) {
            int row = bm + warp_m * 32 + mt * 16 + h * 8 + qr;
            float* dst = g_cur + (size_t)row * OUT_DIM + bn + warp_n * 32 + qc;
#pragma unroll
            for (int nf = 0; nf < 4; nf++) {
                float2 v = *reinterpret_cast<float2*>(dst + nf * 8);
                v.x = __fadd_rn(v.x, __fadd_rn(accsA[mt][nf][h*2+0], accsB[mt][nf][h*2+0]));
                v.y = __fadd_rn(v.y, __fadd_rn(accsA[mt][nf][h*2+1], accsB[mt][nf][h*2+1]));
                *reinterpret_cast<float2*>(dst + nf * 8) = v;
            }
        }
}

// ------------------------------ LIF scan -----------------------------------
__global__ __launch_bounds__(256) void lif_scan_kernel(float* __restrict__ out)
{
    const int idx = blockIdx.x * blockDim.x + threadIdx.x;
    const int BO  = B_DIM * OUT_DIM;
    float mem = 0.0f;
#pragma unroll
    for (int t = 0; t < T_DIM; t++) {
        float c = g_cur[(size_t)t * BO + idx];
        mem = __fadd_rn(__fmul_rn(mem, DECAY_V), c);
        float spk = (__fadd_rn(mem, -THR_V) > 0.0f) ? 1.0f : 0.0f;
        mem = __fadd_rn(mem, -spk * THR_V);
        out[(size_t)t * BO + idx] = spk;
    }
}

// ---------------------------------------------------------------------------
extern "C" void kernel_launch(void* const* d_in, const int* in_sizes, int n_in,
                              void* d_out, int out_size)
{
    const float* x = (const float*)d_in[0];
    const float* W = (const float*)d_in[1];
    const float* b = (const float*)d_in[2];
    float* out = (float*)d_out;

    split_x_kernel<<<(M_DIM * (size_t)IN_DIM / 4) / 256, 256>>>(x);
    split_w_kernel<<<(OUT_DIM * (size_t)IN_DIM / 4) / 256, 256>>>(W);

    dim3 grid(OUT_DIM / BN, M_DIM / BM);      // (16, 64)

    cudaFuncSetAttribute(gemm_main_kernel,
                         cudaFuncAttributeMaxDynamicSharedMemorySize, K1_SMEM);
    gemm_main_kernel<<<grid, 512, K1_SMEM>>>(b);

    cudaFuncSetAttribute(gemm_small_kernel,
                         cudaFuncAttributeMaxDynamicSharedMemorySize, K2_SMEM);
    gemm_small_kernel<<<grid, 512, K2_SMEM>>>();

    lif_scan_kernel<<<(B_DIM * OUT_DIM) / 256, 256>>>(out);
}

// round 7
// speedup vs baseline: 1.8010x; 1.2444x over previous
#include <cuda_runtime.h>
#include <cuda_bf16.h>
#include <cstdint>

// ---------------------------------------------------------------------------
// LIF layer: cur = X @ W^T + b via bf16x3-split GEMM on mma.sync (HMMA).
// R7: K2 reshaped to 256-thread CTAs, single-buffered smem, 2 CTAs/SM
//     (fill tensor-pipe bubbles). K1 drain switched from per-chunk Kahan to a
//     two-level plain-FADD drain (lo accumulator flushed into hi every 4
//     ktiles) -- 2.7x fewer drain FADDs at ~1.2e-7 total GEMM error.
// ---------------------------------------------------------------------------

constexpr int T_DIM  = 64;
constexpr int B_DIM  = 128;
constexpr int IN_DIM = 2048;
constexpr int OUT_DIM = 2048;
constexpr int M_DIM  = T_DIM * B_DIM;          // 8192
constexpr float THR_V   = 1.0f;
constexpr float DECAY_V = 0.60653065971263342f; // exp(-1/2) rounded to fp32

// ------------------------------ scratch -----------------------------------
__device__ float g_cur[(size_t)M_DIM * OUT_DIM];                 // 64 MB
__device__ __nv_bfloat16 g_A0[(size_t)M_DIM * IN_DIM];           // 32 MB each
__device__ __nv_bfloat16 g_A1[(size_t)M_DIM * IN_DIM];
__device__ __nv_bfloat16 g_A2[(size_t)M_DIM * IN_DIM];
__device__ __nv_bfloat16 g_B0[(size_t)OUT_DIM * IN_DIM];         // 8 MB each
__device__ __nv_bfloat16 g_B1[(size_t)OUT_DIM * IN_DIM];
__device__ __nv_bfloat16 g_B2[(size_t)OUT_DIM * IN_DIM];

// ------------------------------ helpers -----------------------------------
__device__ __forceinline__ uint32_t smem_u32(const void* p) {
    uint32_t a;
    asm("{ .reg .u64 t; cvta.to.shared.u64 t, %1; cvt.u32.u64 %0, t; }"
        : "=r"(a) : "l"(p));
    return a;
}

#define SW128(o) ((o) ^ (((o) >> 3) & 0x70))

__device__ __forceinline__ void ldmx4(uint32_t* r, uint32_t addr) {
    asm volatile("ldmatrix.sync.aligned.m8n8.x4.shared.b16 {%0,%1,%2,%3}, [%4];"
                 : "=r"(r[0]), "=r"(r[1]), "=r"(r[2]), "=r"(r[3]) : "r"(addr));
}
// chained accumulate: d += a*b
__device__ __forceinline__ void mma16816(float* d, const uint32_t* a,
                                         const uint32_t* b) {
    asm volatile(
        "mma.sync.aligned.m16n8k16.row.col.f32.bf16.bf16.f32 "
        "{%0,%1,%2,%3}, {%4,%5,%6,%7}, {%8,%9}, {%0,%1,%2,%3};"
        : "+f"(d[0]), "+f"(d[1]), "+f"(d[2]), "+f"(d[3])
        : "r"(a[0]), "r"(a[1]), "r"(a[2]), "r"(a[3]), "r"(b[0]), "r"(b[1]));
}
// zero-C form: d = a*b
__device__ __forceinline__ void mma16816_z(float* d, const uint32_t* a,
                                           const uint32_t* b) {
    asm volatile(
        "mma.sync.aligned.m16n8k16.row.col.f32.bf16.bf16.f32 "
        "{%0,%1,%2,%3}, {%4,%5,%6,%7}, {%8,%9}, {%10,%11,%12,%13};"
        : "=f"(d[0]), "=f"(d[1]), "=f"(d[2]), "=f"(d[3])
        : "r"(a[0]), "r"(a[1]), "r"(a[2]), "r"(a[3]), "r"(b[0]), "r"(b[1]),
          "f"(0.0f), "f"(0.0f), "f"(0.0f), "f"(0.0f));
}

// ------------------------- split fp32 -> 3x bf16 ---------------------------
__device__ __forceinline__ void split3(float v, __nv_bfloat16& h0,
                                       __nv_bfloat16& h1, __nv_bfloat16& h2) {
    h0 = __float2bfloat16(v);
    float r1 = v - __bfloat162float(h0);
    h1 = __float2bfloat16(r1);
    float r2 = r1 - __bfloat162float(h1);
    h2 = __float2bfloat16(r2);
}

__global__ __launch_bounds__(256) void split_x_kernel(const float* __restrict__ src)
{
    int i = blockIdx.x * blockDim.x + threadIdx.x;
    float4 a = reinterpret_cast<const float4*>(src)[i];
    float v[4] = {a.x, a.y, a.z, a.w};
    __nv_bfloat16 h0[4], h1[4], h2[4];
#pragma unroll
    for (int j = 0; j < 4; j++) split3(v[j], h0[j], h1[j], h2[j]);
    __nv_bfloat162 p;
    p = {h0[0], h0[1]}; reinterpret_cast<__nv_bfloat162*>(g_A0)[2*i  ] = p;
    p = {h0[2], h0[3]}; reinterpret_cast<__nv_bfloat162*>(g_A0)[2*i+1] = p;
    p = {h1[0], h1[1]}; reinterpret_cast<__nv_bfloat162*>(g_A1)[2*i  ] = p;
    p = {h1[2], h1[3]}; reinterpret_cast<__nv_bfloat162*>(g_A1)[2*i+1] = p;
    p = {h2[0], h2[1]}; reinterpret_cast<__nv_bfloat162*>(g_A2)[2*i  ] = p;
    p = {h2[2], h2[3]}; reinterpret_cast<__nv_bfloat162*>(g_A2)[2*i+1] = p;
}

__global__ __launch_bounds__(256) void split_w_kernel(const float* __restrict__ src)
{
    int i = blockIdx.x * blockDim.x + threadIdx.x;
    float4 a = reinterpret_cast<const float4*>(src)[i];
    float v[4] = {a.x, a.y, a.z, a.w};
    __nv_bfloat16 h0[4], h1[4], h2[4];
#pragma unroll
    for (int j = 0; j < 4; j++) split3(v[j], h0[j], h1[j], h2[j]);
    __nv_bfloat162 p;
    p = {h0[0], h0[1]}; reinterpret_cast<__nv_bfloat162*>(g_B0)[2*i  ] = p;
    p = {h0[2], h0[3]}; reinterpret_cast<__nv_bfloat162*>(g_B0)[2*i+1] = p;
    p = {h1[0], h1[1]}; reinterpret_cast<__nv_bfloat162*>(g_B1)[2*i  ] = p;
    p = {h1[2], h1[3]}; reinterpret_cast<__nv_bfloat162*>(g_B1)[2*i+1] = p;
    p = {h2[0], h2[1]}; reinterpret_cast<__nv_bfloat162*>(g_B2)[2*i  ] = p;
    p = {h2[2], h2[3]}; reinterpret_cast<__nv_bfloat162*>(g_B2)[2*i+1] = p;
}

// ------------------------------ common dims --------------------------------
constexpr int BM = 128, BN = 128, BK = 64;
constexpr int NST = IN_DIM / BK;              // 32 ktiles
constexpr int TILE_B = 128 * 128;             // 16 KB per tile (SW128 rows)

// ============================ K1: main a0*b0 ================================
// 512 threads = 16 warps (4 wm x 4 wn), warp tile 32x32, double-buffered.
// Drain: chain-2 TC chunks -> lo (plain FADD), lo -> hi every 4 ktiles.
constexpr int K1_SMEM = 2 * TILE_B * 2;       // 65536

__global__ __launch_bounds__(512, 1)
void gemm_main_kernel(const float* __restrict__ bias)
{
    extern __shared__ char smem[];
    const uint32_t sb = smem_u32(smem);
    const int tid  = threadIdx.x;
    const int wid  = tid >> 5;
    const int lane = tid & 31;
    const int bm = blockIdx.y * BM;
    const int bn = blockIdx.x * BN;
    const int warp_m = wid & 3;
    const int warp_n = wid >> 2;

    const __nv_bfloat16* Asrc = g_A0 + (size_t)bm * IN_DIM;
    const __nv_bfloat16* Bsrc = g_B0 + (size_t)bn * IN_DIM;

    auto stage_load = [&](int s) {
        const int buf = s & 1;
        const int k0 = s * BK;
        uint32_t sA = sb + buf * 2 * TILE_B;
        uint32_t sB = sA + TILE_B;
#pragma unroll
        for (int u = 0; u < 2; u++) {
            int v = tid + 512 * u;              // 0..1023
            int row = v >> 3;
            int c = (v & 7) * 16;
            const void* ga = (const char*)(Asrc + (size_t)row * IN_DIM + k0) + c;
            const void* gb = (const char*)(Bsrc + (size_t)row * IN_DIM + k0) + c;
            uint32_t sw = SW128(row * 128 + c);
            asm volatile("cp.async.cg.shared.global [%0], [%1], 16;" :: "r"(sA + sw), "l"(ga));
            asm volatile("cp.async.cg.shared.global [%0], [%1], 16;" :: "r"(sB + sw), "l"(gb));
        }
        asm volatile("cp.async.commit_group;" ::: "memory");
    };

    float hi[2][4][4], lo[2][4][4];
#pragma unroll
    for (int mt = 0; mt < 2; mt++)
#pragma unroll
        for (int nf = 0; nf < 4; nf++)
#pragma unroll
            for (int j = 0; j < 4; j++) { hi[mt][nf][j] = 0.0f; lo[mt][nf][j] = 0.0f; }

    stage_load(0);
    const int mi = lane >> 3, r8 = lane & 7;

    for (int s = 0; s < NST; s++) {
        if (s + 1 < NST) {
            stage_load(s + 1);
            asm volatile("cp.async.wait_group 1;" ::: "memory");
        } else {
            asm volatile("cp.async.wait_group 0;" ::: "memory");
        }
        __syncthreads();

        const uint32_t sA = sb + (s & 1) * 2 * TILE_B;
        const uint32_t sB = sA + TILE_B;

#pragma unroll
        for (int kp = 0; kp < 2; kp++) {        // 2 chain-2 pairs per ktile
            uint32_t af[2][2][4];
            uint32_t bfr[2][2][4];
#pragma unroll
            for (int j = 0; j < 2; j++) {
                int kb_a = (kp * 2 + j) * 32 + (mi >> 1) * 16;
                int kb_b = (kp * 2 + j) * 32 + (mi & 1) * 16;
#pragma unroll
                for (int mt = 0; mt < 2; mt++) {
                    int row = warp_m * 32 + mt * 16 + (mi & 1) * 8 + r8;
                    ldmx4(af[j][mt], sA + SW128(row * 128 + kb_a));
                }
#pragma unroll
                for (int np = 0; np < 2; np++) {
                    int n = warp_n * 32 + np * 16 + (mi >> 1) * 8 + r8;
                    ldmx4(bfr[j][np], sB + SW128(n * 128 + kb_b));
                }
            }
#pragma unroll
            for (int mt = 0; mt < 2; mt++)
#pragma unroll
                for (int nf = 0; nf < 4; nf++) {
                    float tmp[4];
                    mma16816_z(tmp, af[0][mt], &bfr[0][nf >> 1][(nf & 1) * 2]);
                    mma16816 (tmp, af[1][mt], &bfr[1][nf >> 1][(nf & 1) * 2]);
#pragma unroll
                    for (int j = 0; j < 4; j++)
                        lo[mt][nf][j] = __fadd_rn(lo[mt][nf][j], tmp[j]);
                }
        }

        if ((s & 3) == 3) {                     // flush lo -> hi every 4 ktiles
#pragma unroll
            for (int mt = 0; mt < 2; mt++)
#pragma unroll
                for (int nf = 0; nf < 4; nf++)
#pragma unroll
                    for (int j = 0; j < 4; j++) {
                        hi[mt][nf][j] = __fadd_rn(hi[mt][nf][j], lo[mt][nf][j]);
                        lo[mt][nf][j] = 0.0f;
                    }
        }
        __syncthreads();
    }

    // Epilogue: hi + bias -> g_cur  (lo already flushed on last ktile)
    const int qr = lane >> 2;
    const int qc = (lane & 3) * 2;
#pragma unroll
    for (int mt = 0; mt < 2; mt++)
#pragma unroll
        for (int h = 0; h < 2; h++) {
            int row = bm + warp_m * 32 + mt * 16 + h * 8 + qr;
            float* dst = g_cur + (size_t)row * OUT_DIM + bn + warp_n * 32 + qc;
            const float* bp = bias + bn + warp_n * 32 + qc;
#pragma unroll
            for (int nf = 0; nf < 4; nf++) {
                float2 v;
                v.x = __fadd_rn(hi[mt][nf][h*2+0], bp[nf*8+0]);
                v.y = __fadd_rn(hi[mt][nf][h*2+1], bp[nf*8+1]);
                *reinterpret_cast<float2*>(dst + nf * 8) = v;
            }
        }
}

// ====================== K2: 5 small split-combos ============================
// 256 threads = 8 warps (4 wm x 2 wn), warp tile 32x64.
// Single-buffered 6 tiles = 96 KB -> 2 CTAs/SM for cross-CTA overlap.
constexpr int K2_SMEM = 6 * TILE_B;           // 98304

__global__ __launch_bounds__(256, 2)
void gemm_small_kernel()
{
    extern __shared__ char smem[];
    const uint32_t sb = smem_u32(smem);
    const int tid  = threadIdx.x;
    const int wid  = tid >> 5;
    const int lane = tid & 31;
    const int bm = blockIdx.y * BM;
    const int bn = blockIdx.x * BN;
    const int warp_m = wid & 3;      // 0..3
    const int warp_n = wid >> 2;     // 0..1

    const __nv_bfloat16* src[6] = {
        g_A0 + (size_t)bm * IN_DIM, g_A1 + (size_t)bm * IN_DIM,
        g_A2 + (size_t)bm * IN_DIM,
        g_B0 + (size_t)bn * IN_DIM, g_B1 + (size_t)bn * IN_DIM,
        g_B2 + (size_t)bn * IN_DIM };

    auto stage_load = [&](int s) {
        const int k0 = s * BK;
#pragma unroll
        for (int t = 0; t < 6; t++) {
            const __nv_bfloat16* base = src[t] + k0;
            uint32_t stile = sb + t * TILE_B;
#pragma unroll
            for (int u = 0; u < 4; u++) {
                int v = tid + 256 * u;          // 0..1023
                int row = v >> 3;
                int c = (v & 7) * 16;
                const void* g = (const char*)(base + (size_t)row * IN_DIM) + c;
                asm volatile("cp.async.cg.shared.global [%0], [%1], 16;"
                             :: "r"(stile + SW128(row * 128 + c)), "l"(g));
            }
        }
        asm volatile("cp.async.commit_group;" ::: "memory");
    };

    float accs[2][8][4];
#pragma unroll
    for (int mt = 0; mt < 2; mt++)
#pragma unroll
        for (int nf = 0; nf < 8; nf++)
#pragma unroll
            for (int j = 0; j < 4; j++) accs[mt][nf][j] = 0.0f;

    const int mi = lane >> 3, r8 = lane & 7;

    stage_load(0);

    for (int s = 0; s < NST; s++) {
        asm volatile("cp.async.wait_group 0;" ::: "memory");
        __syncthreads();

#pragma unroll
        for (int ks = 0; ks < 4; ks++) {
            uint32_t af[3][2][4];
#pragma unroll
            for (int t = 0; t < 3; t++)
#pragma unroll
                for (int mt = 0; mt < 2; mt++) {
                    int row = warp_m * 32 + mt * 16 + (mi & 1) * 8 + r8;
                    int kb  = ks * 32 + (mi >> 1) * 16;
                    ldmx4(af[t][mt], sb + t * TILE_B + SW128(row * 128 + kb));
                }
            const int kb_b = ks * 32 + (mi & 1) * 16;
            uint32_t bfr[4][4];
            // b-split pairings: b0:{a1,a2}, b1:{a0,a1}, b2:{a0}
            constexpr int NA[3]    = {2, 2, 1};
            constexpr int AI[3][2] = {{1, 2}, {0, 1}, {0, 0}};
#pragma unroll
            for (int bsp = 0; bsp < 3; bsp++) {
#pragma unroll
                for (int np = 0; np < 4; np++) {
                    int n = warp_n * 64 + np * 16 + (mi >> 1) * 8 + r8;
                    ldmx4(bfr[np], sb + (3 + bsp) * TILE_B + SW128(n * 128 + kb_b));
                }
#pragma unroll
                for (int ai = 0; ai < 2; ai++) {
                    if (ai < NA[bsp]) {
#pragma unroll
                        for (int mt = 0; mt < 2; mt++)
#pragma unroll
                            for (int nf = 0; nf < 8; nf++)
                                mma16816(accs[mt][nf], af[AI[bsp][ai]][mt],
                                         &bfr[nf >> 1][(nf & 1) * 2]);
                    }
                }
            }
        }
        __syncthreads();                        // WAR: compute done before reload
        if (s + 1 < NST) stage_load(s + 1);
    }

    // Epilogue: g_cur += smalls
    const int qr = lane >> 2;
    const int qc = (lane & 3) * 2;
#pragma unroll
    for (int mt = 0; mt < 2; mt++)
#pragma unroll
        for (int h = 0; h < 2; h++) {
            int row = bm + warp_m * 32 + mt * 16 + h * 8 + qr;
            float* dst = g_cur + (size_t)row * OUT_DIM + bn + warp_n * 64 + qc;
#pragma unroll
            for (int nf = 0; nf < 8; nf++) {
                float2 v = *reinterpret_cast<float2*>(dst + nf * 8);
                v.x = __fadd_rn(v.x, accs[mt][nf][h*2+0]);
                v.y = __fadd_rn(v.y, accs[mt][nf][h*2+1]);
                *reinterpret_cast<float2*>(dst + nf * 8) = v;
            }
        }
}

// ------------------------------ LIF scan -----------------------------------
__global__ __launch_bounds__(256) void lif_scan_kernel(float* __restrict__ out)
{
    const int idx = blockIdx.x * blockDim.x + threadIdx.x;
    const int BO  = B_DIM * OUT_DIM;
    float mem = 0.0f;
#pragma unroll
    for (int t = 0; t < T_DIM; t++) {
        float c = g_cur[(size_t)t * BO + idx];
        mem = __fadd_rn(__fmul_rn(mem, DECAY_V), c);
        float spk = (__fadd_rn(mem, -THR_V) > 0.0f) ? 1.0f : 0.0f;
        mem = __fadd_rn(mem, -spk * THR_V);
        out[(size_t)t * BO + idx] = spk;
    }
}

// ---------------------------------------------------------------------------
extern "C" void kernel_launch(void* const* d_in, const int* in_sizes, int n_in,
                              void* d_out, int out_size)
{
    const float* x = (const float*)d_in[0];
    const float* W = (const float*)d_in[1];
    const float* b = (const float*)d_in[2];
    float* out = (float*)d_out;

    split_x_kernel<<<(M_DIM * (size_t)IN_DIM / 4) / 256, 256>>>(x);
    split_w_kernel<<<(OUT_DIM * (size_t)IN_DIM / 4) / 256, 256>>>(W);

    dim3 grid(OUT_DIM / BN, M_DIM / BM);      // (16, 64)

    cudaFuncSetAttribute(gemm_main_kernel,
                         cudaFuncAttributeMaxDynamicSharedMemorySize, K1_SMEM);
    gemm_main_kernel<<<grid, 512, K1_SMEM>>>(b);

    cudaFuncSetAttribute(gemm_small_kernel,
                         cudaFuncAttributeMaxDynamicSharedMemorySize, K2_SMEM);
    gemm_small_kernel<<<grid, 256, K2_SMEM>>>();

    lif_scan_kernel<<<(B_DIM * OUT_DIM) / 256, 256>>>(out);
}